// round 6
// baseline (speedup 1.0000x reference)
#include <cuda_runtime.h>
#include <cuda_bf16.h>
#include <cuda_fp16.h>
#include <math.h>
#include <stdint.h>

// Problem constants (fixed by the dataset).
constexpr int NN = 10000;          // nodes
constexpr int DD = 512;            // feature dim = H*C
constexpr int EE = 160000;         // edges
constexpr int ET = EE + NN;        // edges + self loops
constexpr int MPAD = 10112;        // 79 * 128

// Scratch (no cudaMalloc allowed) ------------------------------------------
__device__ __half g_XLh[MPAD * DD];        // x @ W_l (fp16, gathered by aggregate)
__device__ float  g_XR[MPAD * DD];         // x @ W_r (fp32)
__device__ __nv_bfloat16 g_xhi[MPAD * DD]; // bf16 split of x
__device__ __nv_bfloat16 g_xlo[MPAD * DD];
__device__ __nv_bfloat16 g_wthi[2 * DD * DD]; // W^T (K-major [n][k]) bf16 hi, {W_l, W_r}
__device__ __nv_bfloat16 g_wtlo[2 * DD * DD];
__device__ int g_counts[NN];               // static-zero; scatter re-zeroes each run
__device__ int g_rowptr[NN + 1];
__device__ int g_cursor[NN];
__device__ int g_src[ET];

// ---------------------------------------------------------------------------
// helpers
// ---------------------------------------------------------------------------
__device__ __forceinline__ uint32_t smem_u32(const void* p) {
    uint32_t a;
    asm("{ .reg .u64 t; cvta.to.shared.u64 t, %1; cvt.u32.u64 %0, t; }" : "=r"(a) : "l"(p));
    return a;
}
__device__ __forceinline__ void cp_async16(uint32_t sdst, const void* gsrc) {
    asm volatile("cp.async.cg.shared.global [%0], [%1], 16;"
                 :: "r"(sdst), "l"(__cvta_generic_to_global(gsrc)) : "memory");
}
__device__ __forceinline__ void cp_commit() {
    asm volatile("cp.async.commit_group;" ::: "memory");
}
template <int N>
__device__ __forceinline__ void cp_wait() {
    asm volatile("cp.async.wait_group %0;" :: "n"(N) : "memory");
}
__device__ __forceinline__ void ldm_x4(uint32_t& r0, uint32_t& r1, uint32_t& r2, uint32_t& r3,
                                       uint32_t addr) {
    asm volatile("ldmatrix.sync.aligned.m8n8.x4.shared.b16 {%0,%1,%2,%3}, [%4];"
                 : "=r"(r0), "=r"(r1), "=r"(r2), "=r"(r3) : "r"(addr));
}
__device__ __forceinline__ void mma_bf16(float* c, const uint32_t* a, const uint32_t* b) {
    asm volatile(
        "mma.sync.aligned.m16n8k16.row.col.f32.bf16.bf16.f32 "
        "{%0,%1,%2,%3}, {%4,%5,%6,%7}, {%8,%9}, {%0,%1,%2,%3};"
        : "+f"(c[0]), "+f"(c[1]), "+f"(c[2]), "+f"(c[3])
        : "r"(a[0]), "r"(a[1]), "r"(a[2]), "r"(a[3]), "r"(b[0]), "r"(b[1]));
}

// ---------------------------------------------------------------------------
// Prep: split x into bf16 hi/lo (rows >= NN zero-padded)
// ---------------------------------------------------------------------------
__global__ __launch_bounds__(256) void conv_x_kernel(const float* __restrict__ x) {
    int idx = blockIdx.x * blockDim.x + threadIdx.x;  // one float4
    if (idx >= MPAD * DD / 4) return;
    const int e = idx * 4;
    const int row = e >> 9;
    float4 v = make_float4(0.f, 0.f, 0.f, 0.f);
    if (row < NN) v = *(const float4*)(x + e);
    float vv[4] = {v.x, v.y, v.z, v.w};
    __nv_bfloat16 h[4], l[4];
#pragma unroll
    for (int i = 0; i < 4; i++) {
        h[i] = __float2bfloat16_rn(vv[i]);
        l[i] = __float2bfloat16_rn(vv[i] - __bfloat162float(h[i]));
    }
    ((__nv_bfloat162*)(g_xhi + e))[0] = __nv_bfloat162(h[0], h[1]);
    ((__nv_bfloat162*)(g_xhi + e))[1] = __nv_bfloat162(h[2], h[3]);
    ((__nv_bfloat162*)(g_xlo + e))[0] = __nv_bfloat162(l[0], l[1]);
    ((__nv_bfloat162*)(g_xlo + e))[1] = __nv_bfloat162(l[2], l[3]);
}

// Prep: transpose W ([k][n] -> [n][k]) and split into bf16 hi/lo.
__global__ __launch_bounds__(256) void conv_w_kernel(const float* __restrict__ Wl,
                                                     const float* __restrict__ Wr) {
    __shared__ float tile[32][33];
    const float* W = blockIdx.z ? Wr : Wl;
    const int n0 = blockIdx.x * 32;
    const int k0 = blockIdx.y * 32;
    const int tx = threadIdx.x, ty = threadIdx.y;
#pragma unroll
    for (int r = 0; r < 4; r++) {
        int k = k0 + ty + r * 8;
        tile[ty + r * 8][tx] = W[(size_t)k * DD + n0 + tx];
    }
    __syncthreads();
    const size_t base = (size_t)blockIdx.z * DD * DD;
#pragma unroll
    for (int r = 0; r < 4; r++) {
        int n = n0 + ty + r * 8;
        float v = tile[tx][ty + r * 8];
        __nv_bfloat16 h = __float2bfloat16_rn(v);
        __nv_bfloat16 l = __float2bfloat16_rn(v - __bfloat162float(h));
        g_wthi[base + (size_t)n * DD + k0 + tx] = h;
        g_wtlo[base + (size_t)n * DD + k0 + tx] = l;
    }
}

// ---------------------------------------------------------------------------
// mma.sync bf16 split GEMM: C = x @ W  (A row-major K-contig, B = W^T K-contig)
// BM=128, BN=64, BK=16, 256 threads, warps 4(m) x 2(n), warp tile 32x32.
// Double-buffered cp.async. acc += Ahi*Bhi + Alo*Bhi + Ahi*Blo.
// z=0 writes fp16 XL, z=1 writes fp32 XR.
// ---------------------------------------------------------------------------
constexpr int BM = 128, BN = 64, BK = 16;
constexpr int PITCH = 48;                   // bytes per smem row (32B data + 16B pad)
constexpr int SZ_A = BM * PITCH;            // 6144
constexpr int SZ_B = BN * PITCH;            // 3072
constexpr int OFF_AHI = 0;
constexpr int OFF_ALO = SZ_A;
constexpr int OFF_BHI = 2 * SZ_A;
constexpr int OFF_BLO = 2 * SZ_A + SZ_B;
constexpr int STAGE = 2 * SZ_A + 2 * SZ_B;  // 18432

__global__ __launch_bounds__(256) void mma_gemm_kernel() {
    extern __shared__ char smem[];
    const uint32_t sbase = smem_u32(smem);
    const int tid = threadIdx.x;
    const int wid = tid >> 5;
    const int lane = tid & 31;
    const int warp_m = (wid & 3) * 32;      // 0,32,64,96
    const int warp_n = (wid >> 2) * 32;     // 0,32

    const int brow = blockIdx.y * BM;
    const int bn = blockIdx.x * BN;
    const int z = blockIdx.z;
    const __nv_bfloat16* Bhi = g_wthi + (size_t)z * DD * DD;
    const __nv_bfloat16* Blo = g_wtlo + (size_t)z * DD * DD;

    // cp.async mappings (16B chunks; each row of BK=16 bf16 = 32B = 2 chunks)
    const int a_row = tid >> 1;             // 0..127
    const int a_c = (tid & 1);              // chunk
    const int b_row = (tid & 127) >> 1;     // 0..63 (threads 0..127)
    const int b_c = (tid & 1);

    auto load_stage = [&](int kc, int s) {
        const uint32_t st = sbase + s * STAGE;
        const size_t ga = (size_t)(brow + a_row) * DD + kc * BK + a_c * 8;
        cp_async16(st + OFF_AHI + a_row * PITCH + a_c * 16, g_xhi + ga);
        cp_async16(st + OFF_ALO + a_row * PITCH + a_c * 16, g_xlo + ga);
        if (tid < 128) {
            const size_t gb = (size_t)(bn + b_row) * DD + kc * BK + b_c * 8;
            cp_async16(st + OFF_BHI + b_row * PITCH + b_c * 16, Bhi + gb);
            cp_async16(st + OFF_BLO + b_row * PITCH + b_c * 16, Blo + gb);
        }
        cp_commit();
    };

    float acc[2][4][4];
#pragma unroll
    for (int m = 0; m < 2; m++)
#pragma unroll
        for (int n = 0; n < 4; n++)
#pragma unroll
            for (int q = 0; q < 4; q++) acc[m][n][q] = 0.f;

    // ldmatrix lane addressing
    const int ar = lane & 15, ah = lane >> 4;               // A: row, k-half
    const int bi = lane & 7, bs = lane >> 3;                // B: row-in-8, selector
    const uint32_t a_off = (uint32_t)((warp_m + ar) * PITCH + ah * 16);
    const uint32_t b_off = (uint32_t)((warp_n + (bs >> 1) * 8 + bi) * PITCH + (bs & 1) * 16);

    constexpr int NKC = DD / BK;            // 32
    load_stage(0, 0);

    for (int kc = 0; kc < NKC; kc++) {
        if (kc + 1 < NKC) {
            load_stage(kc + 1, (kc + 1) & 1);
            cp_wait<1>();
        } else {
            cp_wait<0>();
        }
        __syncthreads();

        const uint32_t st = sbase + (kc & 1) * STAGE;
        uint32_t ahi[2][4], alo[2][4], bhi[2][4], blo[2][4];
#pragma unroll
        for (int m = 0; m < 2; m++) {
            ldm_x4(ahi[m][0], ahi[m][1], ahi[m][2], ahi[m][3],
                   st + OFF_AHI + a_off + m * 16 * PITCH);
            ldm_x4(alo[m][0], alo[m][1], alo[m][2], alo[m][3],
                   st + OFF_ALO + a_off + m * 16 * PITCH);
        }
#pragma unroll
        for (int g = 0; g < 2; g++) {
            ldm_x4(bhi[g][0], bhi[g][1], bhi[g][2], bhi[g][3],
                   st + OFF_BHI + b_off + g * 16 * PITCH);
            ldm_x4(blo[g][0], blo[g][1], blo[g][2], blo[g][3],
                   st + OFF_BLO + b_off + g * 16 * PITCH);
        }
#pragma unroll
        for (int m = 0; m < 2; m++) {
#pragma unroll
            for (int n = 0; n < 4; n++) {
                const uint32_t* bh = &bhi[n >> 1][(n & 1) * 2];
                const uint32_t* bl = &blo[n >> 1][(n & 1) * 2];
                mma_bf16(acc[m][n], ahi[m], bh);
                mma_bf16(acc[m][n], alo[m], bh);
                mma_bf16(acc[m][n], ahi[m], bl);
            }
        }
        __syncthreads();
    }

    // Epilogue
    const int cr = lane >> 2;               // 0..7
    const int cc = (lane & 3) * 2;
    if (z == 0) {
        // XL -> fp16 (half2 stores)
#pragma unroll
        for (int m = 0; m < 2; m++) {
#pragma unroll
            for (int half = 0; half < 2; half++) {
                const int gm = brow + warp_m + m * 16 + cr + half * 8;
                if (gm < NN) {
                    __half* dst = g_XLh + (size_t)gm * DD + bn + warp_n + cc;
#pragma unroll
                    for (int n = 0; n < 4; n++) {
                        *(__half2*)(dst + n * 8) =
                            __floats2half2_rn(acc[m][n][half * 2], acc[m][n][half * 2 + 1]);
                    }
                }
            }
        }
    } else {
        // XR -> fp32
#pragma unroll
        for (int m = 0; m < 2; m++) {
#pragma unroll
            for (int half = 0; half < 2; half++) {
                const int gm = brow + warp_m + m * 16 + cr + half * 8;
                if (gm < NN) {
                    float* dst = g_XR + (size_t)gm * DD + bn + warp_n + cc;
#pragma unroll
                    for (int n = 0; n < 4; n++) {
                        *(float2*)(dst + n * 8) =
                            make_float2(acc[m][n][half * 2], acc[m][n][half * 2 + 1]);
                    }
                }
            }
        }
    }
}

// ---------------------------------------------------------------------------
// CSR construction (by dst, self loops appended)
// g_counts starts zero (static init) and is re-zeroed by scatter_kernel each
// run (stream-ordered after scan consumed it), so no zeroing launch is needed.
// ---------------------------------------------------------------------------
__global__ void count_kernel(const int* __restrict__ ei) {
    int e = blockIdx.x * blockDim.x + threadIdx.x;
    if (e >= ET) return;
    int d = (e < EE) ? ei[EE + e] : (e - EE);
    atomicAdd(&g_counts[d], 1);
}

// single-pass scan: 1024 threads x 10 items
__global__ __launch_bounds__(1024) void scan_kernel() {
    __shared__ int wsum[32];
    const int tid = threadIdx.x;
    const int lane = tid & 31;
    const int wid = tid >> 5;
    const int base = tid * 10;
    int v[10];
    int s = 0;
#pragma unroll
    for (int i = 0; i < 10; i++) {
        const int idx = base + i;
        v[i] = (idx < NN) ? g_counts[idx] : 0;
        s += v[i];
    }
    int x = s;
#pragma unroll
    for (int o = 1; o < 32; o <<= 1) {
        int y = __shfl_up_sync(0xffffffffu, x, o);
        if (lane >= o) x += y;
    }
    if (lane == 31) wsum[wid] = x;
    __syncthreads();
    if (wid == 0) {
        int t = wsum[lane];
#pragma unroll
        for (int o = 1; o < 32; o <<= 1) {
            int y = __shfl_up_sync(0xffffffffu, t, o);
            if (lane >= o) t += y;
        }
        wsum[lane] = t;
    }
    __syncthreads();
    int run = (wid ? wsum[wid - 1] : 0) + x - s;   // exclusive prefix for this thread
#pragma unroll
    for (int i = 0; i < 10; i++) {
        const int idx = base + i;
        if (idx < NN) {
            g_rowptr[idx] = run;
            g_cursor[idx] = run;
        }
        run += v[i];
    }
    if (tid == 1023) g_rowptr[NN] = run;
}

__global__ void scatter_kernel(const int* __restrict__ ei) {
    int e = blockIdx.x * blockDim.x + threadIdx.x;
    if (e >= ET) return;
    if (e < NN) g_counts[e] = 0;   // restore zero-invariant for next run
    int d, s;
    if (e < EE) { s = ei[e]; d = ei[EE + e]; }
    else        { s = e - EE; d = e - EE; }
    int pos = atomicAdd(&g_cursor[d], 1);
    g_src[pos] = s;
}

// ---------------------------------------------------------------------------
// Fused gather + online segment-softmax + weighted aggregate + ELU + residual.
// One warp per dst node; lane owns 16 contiguous channels (head = lane/4).
// XL gathered in fp16 (halves L2 traffic).
// ---------------------------------------------------------------------------
__global__ __launch_bounds__(256) void aggregate_kernel(const float* __restrict__ x,
                                                        const float* __restrict__ att,
                                                        const float* __restrict__ bias,
                                                        float* __restrict__ out) {
    const int gw = (blockIdx.x * blockDim.x + threadIdx.x) >> 5;
    if (gw >= NN) return;
    const int lane = threadIdx.x & 31;
    const int bd = lane * 16;

    float a[16], xr[16], acc[16];
#pragma unroll
    for (int q = 0; q < 4; q++) {
        float4 t = *(const float4*)(att + bd + 4 * q);
        a[4 * q] = t.x; a[4 * q + 1] = t.y; a[4 * q + 2] = t.z; a[4 * q + 3] = t.w;
        float4 u = *(const float4*)(g_XR + (size_t)gw * DD + bd + 4 * q);
        xr[4 * q] = u.x; xr[4 * q + 1] = u.y; xr[4 * q + 2] = u.z; xr[4 * q + 3] = u.w;
    }
#pragma unroll
    for (int t = 0; t < 16; t++) acc[t] = 0.f;

    float m = -1e30f, denom = 0.f;
    const int e0 = g_rowptr[gw];
    const int e1 = g_rowptr[gw + 1];

    for (int e = e0; e < e1; e++) {
        const int j = g_src[e];
        // 16 halves = 32 bytes = 2 x int4
        const uint4* p = (const uint4*)(g_XLh + (size_t)j * DD + bd);
        uint4 u0 = p[0];
        uint4 u1 = p[1];
        uint32_t raw[8] = {u0.x, u0.y, u0.z, u0.w, u1.x, u1.y, u1.z, u1.w};
        float xl[16];
#pragma unroll
        for (int q = 0; q < 8; q++) {
            float2 f = __half22float2(*(const __half2*)&raw[q]);
            xl[2 * q] = f.x;
            xl[2 * q + 1] = f.y;
        }
        float part = 0.f;
#pragma unroll
        for (int t = 0; t < 16; t++) {
            float s = xl[t] + xr[t];
            float lr = (s > 0.f) ? s : 0.2f * s;
            part = fmaf(a[t], lr, part);
        }
        part += __shfl_xor_sync(0xffffffffu, part, 1);
        part += __shfl_xor_sync(0xffffffffu, part, 2);

        const float mn = fmaxf(m, part);
        const float corr = __expf(m - mn);
        const float w = __expf(part - mn);
        denom = denom * corr + w;
#pragma unroll
        for (int t = 0; t < 16; t++) acc[t] = fmaf(w, xl[t], acc[t] * corr);
        m = mn;
    }

    const float inv = 1.0f / denom;
    const size_t ob = (size_t)gw * DD + bd;
#pragma unroll
    for (int q = 0; q < 4; q++) {
        float4 xv = *(const float4*)(x + ob + 4 * q);
        float r[4];
#pragma unroll
        for (int u = 0; u < 4; u++) {
            float v = acc[4 * q + u] * inv + bias[bd + 4 * q + u];
            float e = (v > 0.f) ? v : expm1f(v);
            r[u] = e + ((const float*)&xv)[u];
        }
        *(float4*)(out + ob + 4 * q) = make_float4(r[0], r[1], r[2], r[3]);
    }
}

// ---------------------------------------------------------------------------
extern "C" void kernel_launch(void* const* d_in, const int* in_sizes, int n_in,
                              void* d_out, int out_size) {
    const float* x    = (const float*)d_in[0];
    const int*   ei   = (const int*)d_in[1];
    const float* W_l  = (const float*)d_in[2];
    const float* W_r  = (const float*)d_in[3];
    const float* att  = (const float*)d_in[4];
    const float* bias = (const float*)d_in[5];
    float* out = (float*)d_out;

    // 0) prep: bf16 splits + W transpose
    conv_x_kernel<<<(MPAD * DD / 4 + 255) / 256, 256>>>(x);
    conv_w_kernel<<<dim3(DD / 32, DD / 32, 2), dim3(32, 8)>>>(W_l, W_r);

    // 1) mma.sync GEMMs: XL = x@W_l (fp16 out), XR = x@W_r (fp32 out)
    mma_gemm_kernel<<<dim3(DD / BN, MPAD / BM, 2), 256, 2 * STAGE>>>();

    // 2) CSR build by dst (counts pre-zeroed invariant)
    count_kernel<<<(ET + 255) / 256, 256>>>(ei);
    scan_kernel<<<1, 1024>>>();
    scatter_kernel<<<(ET + 255) / 256, 256>>>(ei);

    // 3) fused softmax-aggregate + ELU + residual
    aggregate_kernel<<<(NN * 32 + 255) / 256, 256>>>(x, att, bias, out);
}

// round 7
// speedup vs baseline: 1.3834x; 1.3834x over previous
#include <cuda_runtime.h>
#include <cuda_fp16.h>
#include <math.h>
#include <stdint.h>

// Problem constants (fixed by the dataset).
constexpr int NN = 10000;          // nodes
constexpr int DD = 512;            // feature dim = H*C
constexpr int EE = 160000;         // edges
constexpr int ET = EE + NN;        // edges + self loops
constexpr int MPAD = 10112;        // 79 * 128

// Scratch (no cudaMalloc allowed) ------------------------------------------
__device__ __half g_XLh[MPAD * DD];        // x @ W_l (fp16, gathered by aggregate)
__device__ float  g_XR[MPAD * DD];         // x @ W_r (fp32)
__device__ __half g_xh[MPAD * DD];         // fp16 copy of x (GEMM A operand)
__device__ __half g_wt[2 * DD * DD];       // W^T (K-major [n][k]) fp16, {W_l, W_r}
__device__ int g_counts[NN];               // static-zero; scatter re-zeroes each run
__device__ int g_rowptr[NN + 1];
__device__ int g_cursor[NN];
__device__ int g_src[ET];

// ---------------------------------------------------------------------------
// helpers
// ---------------------------------------------------------------------------
__device__ __forceinline__ uint32_t smem_u32(const void* p) {
    uint32_t a;
    asm("{ .reg .u64 t; cvta.to.shared.u64 t, %1; cvt.u32.u64 %0, t; }" : "=r"(a) : "l"(p));
    return a;
}
__device__ __forceinline__ void cp_async16(uint32_t sdst, const void* gsrc) {
    asm volatile("cp.async.cg.shared.global [%0], [%1], 16;"
                 :: "r"(sdst), "l"(__cvta_generic_to_global(gsrc)) : "memory");
}
__device__ __forceinline__ void cp_commit() {
    asm volatile("cp.async.commit_group;" ::: "memory");
}
template <int N>
__device__ __forceinline__ void cp_wait() {
    asm volatile("cp.async.wait_group %0;" :: "n"(N) : "memory");
}
__device__ __forceinline__ void ldm_x4(uint32_t& r0, uint32_t& r1, uint32_t& r2, uint32_t& r3,
                                       uint32_t addr) {
    asm volatile("ldmatrix.sync.aligned.m8n8.x4.shared.b16 {%0,%1,%2,%3}, [%4];"
                 : "=r"(r0), "=r"(r1), "=r"(r2), "=r"(r3) : "r"(addr));
}
__device__ __forceinline__ void mma_f16(float* c, const uint32_t* a, const uint32_t* b) {
    asm volatile(
        "mma.sync.aligned.m16n8k16.row.col.f32.f16.f16.f32 "
        "{%0,%1,%2,%3}, {%4,%5,%6,%7}, {%8,%9}, {%0,%1,%2,%3};"
        : "+f"(c[0]), "+f"(c[1]), "+f"(c[2]), "+f"(c[3])
        : "r"(a[0]), "r"(a[1]), "r"(a[2]), "r"(a[3]), "r"(b[0]), "r"(b[1]));
}

// ---------------------------------------------------------------------------
// Prep: x -> fp16 (rows >= NN zero-padded)
// ---------------------------------------------------------------------------
__global__ __launch_bounds__(256) void conv_x_kernel(const float* __restrict__ x) {
    int idx = blockIdx.x * blockDim.x + threadIdx.x;  // one float4
    if (idx >= MPAD * DD / 4) return;
    const int e = idx * 4;
    const int row = e >> 9;
    float4 v = make_float4(0.f, 0.f, 0.f, 0.f);
    if (row < NN) v = *(const float4*)(x + e);
    ((__half2*)(g_xh + e))[0] = __floats2half2_rn(v.x, v.y);
    ((__half2*)(g_xh + e))[1] = __floats2half2_rn(v.z, v.w);
}

// Prep: transpose W ([k][n] -> [n][k]) to fp16.
__global__ __launch_bounds__(256) void conv_w_kernel(const float* __restrict__ Wl,
                                                     const float* __restrict__ Wr) {
    __shared__ float tile[32][33];
    const float* W = blockIdx.z ? Wr : Wl;
    const int n0 = blockIdx.x * 32;
    const int k0 = blockIdx.y * 32;
    const int tx = threadIdx.x, ty = threadIdx.y;
#pragma unroll
    for (int r = 0; r < 4; r++) {
        int k = k0 + ty + r * 8;
        tile[ty + r * 8][tx] = W[(size_t)k * DD + n0 + tx];
    }
    __syncthreads();
    const size_t base = (size_t)blockIdx.z * DD * DD;
#pragma unroll
    for (int r = 0; r < 4; r++) {
        int n = n0 + ty + r * 8;
        g_wt[base + (size_t)n * DD + k0 + tx] = __float2half_rn(tile[tx][ty + r * 8]);
    }
}

// ---------------------------------------------------------------------------
// mma.sync fp16 GEMM: C = x @ W  (A row-major K-contig, B = W^T K-contig)
// BM=128, BN=64, BK=16, 256 threads, warps 4(m) x 2(n), warp tile 32x32.
// Double-buffered cp.async. z=0 writes fp16 XL, z=1 writes fp32 XR.
// ---------------------------------------------------------------------------
constexpr int BM = 128, BN = 64, BK = 16;
constexpr int PITCH = 48;                   // bytes per smem row (32B data + 16B pad)
constexpr int SZ_A = BM * PITCH;            // 6144
constexpr int SZ_B = BN * PITCH;            // 3072
constexpr int OFF_A = 0;
constexpr int OFF_B = SZ_A;
constexpr int STAGE = SZ_A + SZ_B;          // 9216

__global__ __launch_bounds__(256) void mma_gemm_kernel() {
    extern __shared__ char smem[];
    const uint32_t sbase = smem_u32(smem);
    const int tid = threadIdx.x;
    const int wid = tid >> 5;
    const int lane = tid & 31;
    const int warp_m = (wid & 3) * 32;      // 0,32,64,96
    const int warp_n = (wid >> 2) * 32;     // 0,32

    const int brow = blockIdx.y * BM;
    const int bn = blockIdx.x * BN;
    const int z = blockIdx.z;
    const __half* Bmat = g_wt + (size_t)z * DD * DD;

    // cp.async mappings (16B chunks; each row of BK=16 halves = 32B = 2 chunks)
    const int a_row = tid >> 1;             // 0..127
    const int a_c = (tid & 1);
    const int b_row = (tid & 127) >> 1;     // 0..63 (threads 0..127)
    const int b_c = (tid & 1);

    auto load_stage = [&](int kc, int s) {
        const uint32_t st = sbase + s * STAGE;
        const size_t ga = (size_t)(brow + a_row) * DD + kc * BK + a_c * 8;
        cp_async16(st + OFF_A + a_row * PITCH + a_c * 16, g_xh + ga);
        if (tid < 128) {
            const size_t gb = (size_t)(bn + b_row) * DD + kc * BK + b_c * 8;
            cp_async16(st + OFF_B + b_row * PITCH + b_c * 16, Bmat + gb);
        }
        cp_commit();
    };

    float acc[2][4][4];
#pragma unroll
    for (int m = 0; m < 2; m++)
#pragma unroll
        for (int n = 0; n < 4; n++)
#pragma unroll
            for (int q = 0; q < 4; q++) acc[m][n][q] = 0.f;

    // ldmatrix lane addressing
    const int ar = lane & 15, ah = lane >> 4;               // A: row, k-half
    const int bi = lane & 7, bs = lane >> 3;                // B: row-in-8, selector
    const uint32_t a_off = (uint32_t)((warp_m + ar) * PITCH + ah * 16);
    const uint32_t b_off = (uint32_t)((warp_n + (bs >> 1) * 8 + bi) * PITCH + (bs & 1) * 16);

    constexpr int NKC = DD / BK;            // 32
    load_stage(0, 0);

    for (int kc = 0; kc < NKC; kc++) {
        if (kc + 1 < NKC) {
            load_stage(kc + 1, (kc + 1) & 1);
            cp_wait<1>();
        } else {
            cp_wait<0>();
        }
        __syncthreads();

        const uint32_t st = sbase + (kc & 1) * STAGE;
        uint32_t am[2][4], bm[2][4];
#pragma unroll
        for (int m = 0; m < 2; m++)
            ldm_x4(am[m][0], am[m][1], am[m][2], am[m][3],
                   st + OFF_A + a_off + m * 16 * PITCH);
#pragma unroll
        for (int g = 0; g < 2; g++)
            ldm_x4(bm[g][0], bm[g][1], bm[g][2], bm[g][3],
                   st + OFF_B + b_off + g * 16 * PITCH);
#pragma unroll
        for (int m = 0; m < 2; m++)
#pragma unroll
            for (int n = 0; n < 4; n++)
                mma_f16(acc[m][n], am[m], &bm[n >> 1][(n & 1) * 2]);
        __syncthreads();
    }

    // Epilogue
    const int cr = lane >> 2;               // 0..7
    const int cc = (lane & 3) * 2;
    if (z == 0) {
#pragma unroll
        for (int m = 0; m < 2; m++) {
#pragma unroll
            for (int half = 0; half < 2; half++) {
                const int gm = brow + warp_m + m * 16 + cr + half * 8;
                if (gm < NN) {
                    __half* dst = g_XLh + (size_t)gm * DD + bn + warp_n + cc;
#pragma unroll
                    for (int n = 0; n < 4; n++) {
                        *(__half2*)(dst + n * 8) =
                            __floats2half2_rn(acc[m][n][half * 2], acc[m][n][half * 2 + 1]);
                    }
                }
            }
        }
    } else {
#pragma unroll
        for (int m = 0; m < 2; m++) {
#pragma unroll
            for (int half = 0; half < 2; half++) {
                const int gm = brow + warp_m + m * 16 + cr + half * 8;
                if (gm < NN) {
                    float* dst = g_XR + (size_t)gm * DD + bn + warp_n + cc;
#pragma unroll
                    for (int n = 0; n < 4; n++) {
                        *(float2*)(dst + n * 8) =
                            make_float2(acc[m][n][half * 2], acc[m][n][half * 2 + 1]);
                    }
                }
            }
        }
    }
}

// ---------------------------------------------------------------------------
// CSR construction (by dst, self loops appended)
// ---------------------------------------------------------------------------
__global__ void count_kernel(const int* __restrict__ ei) {
    int e = blockIdx.x * blockDim.x + threadIdx.x;
    if (e >= ET) return;
    int d = (e < EE) ? ei[EE + e] : (e - EE);
    atomicAdd(&g_counts[d], 1);
}

// single-pass scan: 1024 threads x 10 items
__global__ __launch_bounds__(1024) void scan_kernel() {
    __shared__ int wsum[32];
    const int tid = threadIdx.x;
    const int lane = tid & 31;
    const int wid = tid >> 5;
    const int base = tid * 10;
    int v[10];
    int s = 0;
#pragma unroll
    for (int i = 0; i < 10; i++) {
        const int idx = base + i;
        v[i] = (idx < NN) ? g_counts[idx] : 0;
        s += v[i];
    }
    int x = s;
#pragma unroll
    for (int o = 1; o < 32; o <<= 1) {
        int y = __shfl_up_sync(0xffffffffu, x, o);
        if (lane >= o) x += y;
    }
    if (lane == 31) wsum[wid] = x;
    __syncthreads();
    if (wid == 0) {
        int t = wsum[lane];
#pragma unroll
        for (int o = 1; o < 32; o <<= 1) {
            int y = __shfl_up_sync(0xffffffffu, t, o);
            if (lane >= o) t += y;
        }
        wsum[lane] = t;
    }
    __syncthreads();
    int run = (wid ? wsum[wid - 1] : 0) + x - s;
#pragma unroll
    for (int i = 0; i < 10; i++) {
        const int idx = base + i;
        if (idx < NN) {
            g_rowptr[idx] = run;
            g_cursor[idx] = run;
        }
        run += v[i];
    }
    if (tid == 1023) g_rowptr[NN] = run;
}

__global__ void scatter_kernel(const int* __restrict__ ei) {
    int e = blockIdx.x * blockDim.x + threadIdx.x;
    if (e >= ET) return;
    if (e < NN) g_counts[e] = 0;   // restore zero-invariant for next run
    int d, s;
    if (e < EE) { s = ei[e]; d = ei[EE + e]; }
    else        { s = e - EE; d = e - EE; }
    int pos = atomicAdd(&g_cursor[d], 1);
    g_src[pos] = s;
}

// ---------------------------------------------------------------------------
// Fused gather + online segment-softmax + weighted aggregate + ELU + residual.
// One warp per dst node; lane owns 16 contiguous channels (head = lane/4).
// Next-edge prefetch (MLP=2) to cover L2 gather latency.
// ---------------------------------------------------------------------------
__global__ __launch_bounds__(256) void aggregate_kernel(const float* __restrict__ x,
                                                        const float* __restrict__ att,
                                                        const float* __restrict__ bias,
                                                        float* __restrict__ out) {
    const int gw = (blockIdx.x * blockDim.x + threadIdx.x) >> 5;
    if (gw >= NN) return;
    const int lane = threadIdx.x & 31;
    const int bd = lane * 16;

    float a[16], xr[16], acc[16];
#pragma unroll
    for (int q = 0; q < 4; q++) {
        float4 t = *(const float4*)(att + bd + 4 * q);
        a[4 * q] = t.x; a[4 * q + 1] = t.y; a[4 * q + 2] = t.z; a[4 * q + 3] = t.w;
        float4 u = *(const float4*)(g_XR + (size_t)gw * DD + bd + 4 * q);
        xr[4 * q] = u.x; xr[4 * q + 1] = u.y; xr[4 * q + 2] = u.z; xr[4 * q + 3] = u.w;
    }
#pragma unroll
    for (int t = 0; t < 16; t++) acc[t] = 0.f;

    float m = -1e30f, denom = 0.f;
    const int e0 = g_rowptr[gw];
    const int e1 = g_rowptr[gw + 1];   // e1 > e0 guaranteed (self loop)

    // prefetch first edge
    int j = g_src[e0];
    const uint4* p = (const uint4*)(g_XLh + (size_t)j * DD + bd);
    uint4 u0 = p[0], u1 = p[1];

    for (int e = e0; e < e1; e++) {
        const uint4 c0 = u0, c1 = u1;
        if (e + 1 < e1) {                  // prefetch next edge's row
            const int jn = g_src[e + 1];
            const uint4* pn = (const uint4*)(g_XLh + (size_t)jn * DD + bd);
            u0 = pn[0];
            u1 = pn[1];
        }
        uint32_t raw[8] = {c0.x, c0.y, c0.z, c0.w, c1.x, c1.y, c1.z, c1.w};
        float xl[16];
#pragma unroll
        for (int q = 0; q < 8; q++) {
            float2 f = __half22float2(*(const __half2*)&raw[q]);
            xl[2 * q] = f.x;
            xl[2 * q + 1] = f.y;
        }
        float part = 0.f;
#pragma unroll
        for (int t = 0; t < 16; t++) {
            float s = xl[t] + xr[t];
            float lr = (s > 0.f) ? s : 0.2f * s;
            part = fmaf(a[t], lr, part);
        }
        part += __shfl_xor_sync(0xffffffffu, part, 1);
        part += __shfl_xor_sync(0xffffffffu, part, 2);

        const float mn = fmaxf(m, part);
        const float corr = __expf(m - mn);
        const float w = __expf(part - mn);
        denom = denom * corr + w;
#pragma unroll
        for (int t = 0; t < 16; t++) acc[t] = fmaf(w, xl[t], acc[t] * corr);
        m = mn;
    }

    const float inv = 1.0f / denom;
    const size_t ob = (size_t)gw * DD + bd;
#pragma unroll
    for (int q = 0; q < 4; q++) {
        float4 xv = *(const float4*)(x + ob + 4 * q);
        float r[4];
#pragma unroll
        for (int u = 0; u < 4; u++) {
            float v = acc[4 * q + u] * inv + bias[bd + 4 * q + u];
            float e = (v > 0.f) ? v : expm1f(v);
            r[u] = e + ((const float*)&xv)[u];
        }
        *(float4*)(out + ob + 4 * q) = make_float4(r[0], r[1], r[2], r[3]);
    }
}

// ---------------------------------------------------------------------------
extern "C" void kernel_launch(void* const* d_in, const int* in_sizes, int n_in,
                              void* d_out, int out_size) {
    const float* x    = (const float*)d_in[0];
    const int*   ei   = (const int*)d_in[1];
    const float* W_l  = (const float*)d_in[2];
    const float* W_r  = (const float*)d_in[3];
    const float* att  = (const float*)d_in[4];
    const float* bias = (const float*)d_in[5];
    float* out = (float*)d_out;

    // 0) prep: fp16 conversions + W transpose
    conv_x_kernel<<<(MPAD * DD / 4 + 255) / 256, 256>>>(x);
    conv_w_kernel<<<dim3(DD / 32, DD / 32, 2), dim3(32, 8)>>>(W_l, W_r);

    // 1) fp16 mma.sync GEMMs: XL = x@W_l (fp16 out), XR = x@W_r (fp32 out)
    mma_gemm_kernel<<<dim3(DD / BN, MPAD / BM, 2), 256, 2 * STAGE>>>();

    // 2) CSR build by dst (counts pre-zeroed invariant)
    count_kernel<<<(ET + 255) / 256, 256>>>(ei);
    scan_kernel<<<1, 1024>>>();
    scatter_kernel<<<(ET + 255) / 256, 256>>>(ei);

    // 3) fused softmax-aggregate + ELU + residual
    aggregate_kernel<<<(NN * 32 + 255) / 256, 256>>>(x, att, bias, out);
}

// round 8
// speedup vs baseline: 1.5383x; 1.1120x over previous
#include <cuda_runtime.h>
#include <cuda_fp16.h>
#include <math.h>
#include <stdint.h>

// Problem constants (fixed by the dataset).
constexpr int NN = 10000;          // nodes
constexpr int DD = 512;            // feature dim = H*C
constexpr int EE = 160000;         // edges
constexpr int ET = EE + NN;        // edges + self loops
constexpr int MPAD = 10112;        // 79 * 128

// Scratch (no cudaMalloc allowed) ------------------------------------------
__device__ __half g_XLh[MPAD * DD];        // x @ W_l (fp16, gathered by aggregate)
__device__ float  g_XR[MPAD * DD];         // x @ W_r (fp32)
__device__ __half g_xh[MPAD * DD];         // fp16 copy of x (GEMM A operand)
__device__ __half g_wt[2 * DD * DD];       // W^T (K-major [n][k]) fp16, {W_l, W_r}
__device__ int g_counts[NN];               // static-zero; scatter re-zeroes each run
__device__ int g_rowptr[NN + 1];
__device__ int g_cursor[NN];
__device__ int g_src[ET];

// ---------------------------------------------------------------------------
// helpers
// ---------------------------------------------------------------------------
__device__ __forceinline__ uint32_t smem_u32(const void* p) {
    uint32_t a;
    asm("{ .reg .u64 t; cvta.to.shared.u64 t, %1; cvt.u32.u64 %0, t; }" : "=r"(a) : "l"(p));
    return a;
}
__device__ __forceinline__ void cp_async16(uint32_t sdst, const void* gsrc) {
    asm volatile("cp.async.cg.shared.global [%0], [%1], 16;"
                 :: "r"(sdst), "l"(__cvta_generic_to_global(gsrc)) : "memory");
}
__device__ __forceinline__ void cp_commit() {
    asm volatile("cp.async.commit_group;" ::: "memory");
}
template <int N>
__device__ __forceinline__ void cp_wait() {
    asm volatile("cp.async.wait_group %0;" :: "n"(N) : "memory");
}
__device__ __forceinline__ void ldm_x4(uint32_t& r0, uint32_t& r1, uint32_t& r2, uint32_t& r3,
                                       uint32_t addr) {
    asm volatile("ldmatrix.sync.aligned.m8n8.x4.shared.b16 {%0,%1,%2,%3}, [%4];"
                 : "=r"(r0), "=r"(r1), "=r"(r2), "=r"(r3) : "r"(addr));
}
__device__ __forceinline__ void mma_f16(float* c, const uint32_t* a, const uint32_t* b) {
    asm volatile(
        "mma.sync.aligned.m16n8k16.row.col.f32.f16.f16.f32 "
        "{%0,%1,%2,%3}, {%4,%5,%6,%7}, {%8,%9}, {%0,%1,%2,%3};"
        : "+f"(c[0]), "+f"(c[1]), "+f"(c[2]), "+f"(c[3])
        : "r"(a[0]), "r"(a[1]), "r"(a[2]), "r"(a[3]), "r"(b[0]), "r"(b[1]));
}

// ---------------------------------------------------------------------------
// Prep: x -> fp16 (rows >= NN zero-padded)
// ---------------------------------------------------------------------------
__global__ __launch_bounds__(256) void conv_x_kernel(const float* __restrict__ x) {
    int idx = blockIdx.x * blockDim.x + threadIdx.x;  // one float4
    if (idx >= MPAD * DD / 4) return;
    const int e = idx * 4;
    const int row = e >> 9;
    float4 v = make_float4(0.f, 0.f, 0.f, 0.f);
    if (row < NN) v = *(const float4*)(x + e);
    ((__half2*)(g_xh + e))[0] = __floats2half2_rn(v.x, v.y);
    ((__half2*)(g_xh + e))[1] = __floats2half2_rn(v.z, v.w);
}

// Prep: transpose W ([k][n] -> [n][k]) to fp16.
__global__ __launch_bounds__(256) void conv_w_kernel(const float* __restrict__ Wl,
                                                     const float* __restrict__ Wr) {
    __shared__ float tile[32][33];
    const float* W = blockIdx.z ? Wr : Wl;
    const int n0 = blockIdx.x * 32;
    const int k0 = blockIdx.y * 32;
    const int tx = threadIdx.x, ty = threadIdx.y;
#pragma unroll
    for (int r = 0; r < 4; r++) {
        int k = k0 + ty + r * 8;
        tile[ty + r * 8][tx] = W[(size_t)k * DD + n0 + tx];
    }
    __syncthreads();
    const size_t base = (size_t)blockIdx.z * DD * DD;
#pragma unroll
    for (int r = 0; r < 4; r++) {
        int n = n0 + ty + r * 8;
        g_wt[base + (size_t)n * DD + k0 + tx] = __float2half_rn(tile[tx][ty + r * 8]);
    }
}

// ---------------------------------------------------------------------------
// Fused fp16 GEMM: computes BOTH XL = x@W_l and XR = x@W_r in one CTA
// (A tile loaded/ldmatrix'd once, reused for both weights).
// BM=128, BN=64, BK=16, 256 threads, warps 4(m) x 2(n), warp tile 32x32 per z.
// Double-buffered cp.async.
// ---------------------------------------------------------------------------
constexpr int BM = 128, BN = 64, BK = 16;
constexpr int PITCH = 48;                   // bytes per smem row (32B data + 16B pad)
constexpr int SZ_A = BM * PITCH;            // 6144
constexpr int SZ_B = BN * PITCH;            // 3072 (per z)
constexpr int OFF_A = 0;
constexpr int OFF_B0 = SZ_A;
constexpr int OFF_B1 = SZ_A + SZ_B;
constexpr int STAGE = SZ_A + 2 * SZ_B;      // 12288

__global__ __launch_bounds__(256) void mma_gemm_kernel() {
    extern __shared__ char smem[];
    const uint32_t sbase = smem_u32(smem);
    const int tid = threadIdx.x;
    const int wid = tid >> 5;
    const int lane = tid & 31;
    const int warp_m = (wid & 3) * 32;      // 0,32,64,96
    const int warp_n = (wid >> 2) * 32;     // 0,32

    const int brow = blockIdx.y * BM;
    const int bn = blockIdx.x * BN;

    // cp.async mappings (16B chunks; each row of BK=16 halves = 32B = 2 chunks)
    const int a_row = tid >> 1;             // 0..127
    const int a_c = (tid & 1);
    const int b_z = tid >> 7;               // 0/1 weight select
    const int b_row = (tid & 127) >> 1;     // 0..63
    const int b_c = (tid & 1);
    const __half* Bsrc = g_wt + (size_t)b_z * DD * DD;
    const uint32_t b_dst_off = b_z ? OFF_B1 : OFF_B0;

    auto load_stage = [&](int kc, int s) {
        const uint32_t st = sbase + s * STAGE;
        const size_t ga = (size_t)(brow + a_row) * DD + kc * BK + a_c * 8;
        cp_async16(st + OFF_A + a_row * PITCH + a_c * 16, g_xh + ga);
        const size_t gb = (size_t)(bn + b_row) * DD + kc * BK + b_c * 8;
        cp_async16(st + b_dst_off + b_row * PITCH + b_c * 16, Bsrc + gb);
        cp_commit();
    };

    float acc[2][2][4][4];                  // [z][m][n][q]
#pragma unroll
    for (int z = 0; z < 2; z++)
#pragma unroll
        for (int m = 0; m < 2; m++)
#pragma unroll
            for (int n = 0; n < 4; n++)
#pragma unroll
                for (int q = 0; q < 4; q++) acc[z][m][n][q] = 0.f;

    // ldmatrix lane addressing
    const int ar = lane & 15, ah = lane >> 4;               // A: row, k-half
    const int bi = lane & 7, bs = lane >> 3;                // B: row-in-8, selector
    const uint32_t a_off = (uint32_t)((warp_m + ar) * PITCH + ah * 16);
    const uint32_t b_off = (uint32_t)((warp_n + (bs >> 1) * 8 + bi) * PITCH + (bs & 1) * 16);

    constexpr int NKC = DD / BK;            // 32
    load_stage(0, 0);

    for (int kc = 0; kc < NKC; kc++) {
        if (kc + 1 < NKC) {
            load_stage(kc + 1, (kc + 1) & 1);
            cp_wait<1>();
        } else {
            cp_wait<0>();
        }
        __syncthreads();

        const uint32_t st = sbase + (kc & 1) * STAGE;
        uint32_t am[2][4], bm[2][2][4];
#pragma unroll
        for (int m = 0; m < 2; m++)
            ldm_x4(am[m][0], am[m][1], am[m][2], am[m][3],
                   st + OFF_A + a_off + m * 16 * PITCH);
#pragma unroll
        for (int g = 0; g < 2; g++) {
            ldm_x4(bm[0][g][0], bm[0][g][1], bm[0][g][2], bm[0][g][3],
                   st + OFF_B0 + b_off + g * 16 * PITCH);
            ldm_x4(bm[1][g][0], bm[1][g][1], bm[1][g][2], bm[1][g][3],
                   st + OFF_B1 + b_off + g * 16 * PITCH);
        }
#pragma unroll
        for (int z = 0; z < 2; z++)
#pragma unroll
            for (int m = 0; m < 2; m++)
#pragma unroll
                for (int n = 0; n < 4; n++)
                    mma_f16(acc[z][m][n], am[m], &bm[z][n >> 1][(n & 1) * 2]);
        __syncthreads();
    }

    // Epilogue: z=0 -> fp16 XL, z=1 -> fp32 XR
    const int cr = lane >> 2;               // 0..7
    const int cc = (lane & 3) * 2;
#pragma unroll
    for (int m = 0; m < 2; m++) {
#pragma unroll
        for (int half = 0; half < 2; half++) {
            const int gm = brow + warp_m + m * 16 + cr + half * 8;
            if (gm < NN) {
                __half* dst0 = g_XLh + (size_t)gm * DD + bn + warp_n + cc;
                float* dst1 = g_XR + (size_t)gm * DD + bn + warp_n + cc;
#pragma unroll
                for (int n = 0; n < 4; n++) {
                    *(__half2*)(dst0 + n * 8) = __floats2half2_rn(
                        acc[0][m][n][half * 2], acc[0][m][n][half * 2 + 1]);
                    *(float2*)(dst1 + n * 8) = make_float2(
                        acc[1][m][n][half * 2], acc[1][m][n][half * 2 + 1]);
                }
            }
        }
    }
}

// ---------------------------------------------------------------------------
// CSR construction (by dst, self loops appended)
// ---------------------------------------------------------------------------
__global__ void count_kernel(const int* __restrict__ ei) {
    int e = blockIdx.x * blockDim.x + threadIdx.x;
    if (e >= ET) return;
    int d = (e < EE) ? ei[EE + e] : (e - EE);
    atomicAdd(&g_counts[d], 1);
}

// single-pass scan: 1024 threads x 10 items
__global__ __launch_bounds__(1024) void scan_kernel() {
    __shared__ int wsum[32];
    const int tid = threadIdx.x;
    const int lane = tid & 31;
    const int wid = tid >> 5;
    const int base = tid * 10;
    int v[10];
    int s = 0;
#pragma unroll
    for (int i = 0; i < 10; i++) {
        const int idx = base + i;
        v[i] = (idx < NN) ? g_counts[idx] : 0;
        s += v[i];
    }
    int x = s;
#pragma unroll
    for (int o = 1; o < 32; o <<= 1) {
        int y = __shfl_up_sync(0xffffffffu, x, o);
        if (lane >= o) x += y;
    }
    if (lane == 31) wsum[wid] = x;
    __syncthreads();
    if (wid == 0) {
        int t = wsum[lane];
#pragma unroll
        for (int o = 1; o < 32; o <<= 1) {
            int y = __shfl_up_sync(0xffffffffu, t, o);
            if (lane >= o) t += y;
        }
        wsum[lane] = t;
    }
    __syncthreads();
    int run = (wid ? wsum[wid - 1] : 0) + x - s;
#pragma unroll
    for (int i = 0; i < 10; i++) {
        const int idx = base + i;
        if (idx < NN) {
            g_rowptr[idx] = run;
            g_cursor[idx] = run;
        }
        run += v[i];
    }
    if (tid == 1023) g_rowptr[NN] = run;
}

__global__ void scatter_kernel(const int* __restrict__ ei) {
    int e = blockIdx.x * blockDim.x + threadIdx.x;
    if (e >= ET) return;
    if (e < NN) g_counts[e] = 0;   // restore zero-invariant for next run
    int d, s;
    if (e < EE) { s = ei[e]; d = ei[EE + e]; }
    else        { s = e - EE; d = e - EE; }
    int pos = atomicAdd(&g_cursor[d], 1);
    g_src[pos] = s;
}

// ---------------------------------------------------------------------------
// Fused gather + online segment-softmax + weighted aggregate + ELU + residual.
// One warp per dst node; lane owns 16 contiguous channels (head = lane/4).
// Pair-at-a-time edge processing + next-pair prefetch (MLP up to 4).
// ---------------------------------------------------------------------------
__global__ __launch_bounds__(256) void aggregate_kernel(const float* __restrict__ x,
                                                        const float* __restrict__ att,
                                                        const float* __restrict__ bias,
                                                        float* __restrict__ out) {
    const int gw = (blockIdx.x * blockDim.x + threadIdx.x) >> 5;
    if (gw >= NN) return;
    const int lane = threadIdx.x & 31;
    const int bd = lane * 16;

    float a[16], xr[16], acc[16];
#pragma unroll
    for (int q = 0; q < 4; q++) {
        float4 t = *(const float4*)(att + bd + 4 * q);
        a[4 * q] = t.x; a[4 * q + 1] = t.y; a[4 * q + 2] = t.z; a[4 * q + 3] = t.w;
        float4 u = *(const float4*)(g_XR + (size_t)gw * DD + bd + 4 * q);
        xr[4 * q] = u.x; xr[4 * q + 1] = u.y; xr[4 * q + 2] = u.z; xr[4 * q + 3] = u.w;
    }
#pragma unroll
    for (int t = 0; t < 16; t++) acc[t] = 0.f;

    float m = -1e30f, denom = 0.f;
    const int e0 = g_rowptr[gw];
    const int e1 = g_rowptr[gw + 1];   // e1 > e0 guaranteed (self loop)

    auto row_ptr = [&](int e) {
        return (const uint4*)(g_XLh + (size_t)g_src[e] * DD + bd);
    };

    // online softmax update for one loaded row (2 x uint4 of halves)
    auto process = [&](uint4 c0, uint4 c1) {
        uint32_t raw[8] = {c0.x, c0.y, c0.z, c0.w, c1.x, c1.y, c1.z, c1.w};
        float xl[16];
#pragma unroll
        for (int q = 0; q < 8; q++) {
            float2 f = __half22float2(*(const __half2*)&raw[q]);
            xl[2 * q] = f.x;
            xl[2 * q + 1] = f.y;
        }
        float part = 0.f;
#pragma unroll
        for (int t = 0; t < 16; t++) {
            float s = xl[t] + xr[t];
            float lr = (s > 0.f) ? s : 0.2f * s;
            part = fmaf(a[t], lr, part);
        }
        part += __shfl_xor_sync(0xffffffffu, part, 1);
        part += __shfl_xor_sync(0xffffffffu, part, 2);
        const float mn = fmaxf(m, part);
        const float corr = __expf(m - mn);
        const float w = __expf(part - mn);
        denom = denom * corr + w;
#pragma unroll
        for (int t = 0; t < 16; t++) acc[t] = fmaf(w, xl[t], acc[t] * corr);
        m = mn;
    };

    int e = e0;
    int rem = e1 - e0;
    // prefetch first pair
    uint4 p0a, p0b, p1a, p1b;
    {
        const uint4* p = row_ptr(e);
        p0a = p[0]; p0b = p[1];
        if (rem > 1) {
            const uint4* q = row_ptr(e + 1);
            p1a = q[0]; p1b = q[1];
        }
    }
    while (rem >= 2) {
        const uint4 c0a = p0a, c0b = p0b, c1a = p1a, c1b = p1b;
        const int nx = e + 2;
        const int nrem = rem - 2;
        if (nrem > 0) {                      // prefetch next pair
            const uint4* p = row_ptr(nx);
            p0a = p[0]; p0b = p[1];
            if (nrem > 1) {
                const uint4* q = row_ptr(nx + 1);
                p1a = q[0]; p1b = q[1];
            }
        }
        process(c0a, c0b);
        process(c1a, c1b);
        e = nx;
        rem = nrem;
    }
    if (rem == 1) process(p0a, p0b);

    const float inv = 1.0f / denom;
    const size_t ob = (size_t)gw * DD + bd;
#pragma unroll
    for (int q = 0; q < 4; q++) {
        float4 xv = *(const float4*)(x + ob + 4 * q);
        float r[4];
#pragma unroll
        for (int u = 0; u < 4; u++) {
            float v = acc[4 * q + u] * inv + bias[bd + 4 * q + u];
            float e2 = (v > 0.f) ? v : expm1f(v);
            r[u] = e2 + ((const float*)&xv)[u];
        }
        *(float4*)(out + ob + 4 * q) = make_float4(r[0], r[1], r[2], r[3]);
    }
}

// ---------------------------------------------------------------------------
extern "C" void kernel_launch(void* const* d_in, const int* in_sizes, int n_in,
                              void* d_out, int out_size) {
    const float* x    = (const float*)d_in[0];
    const int*   ei   = (const int*)d_in[1];
    const float* W_l  = (const float*)d_in[2];
    const float* W_r  = (const float*)d_in[3];
    const float* att  = (const float*)d_in[4];
    const float* bias = (const float*)d_in[5];
    float* out = (float*)d_out;

    // 0) prep: fp16 conversions + W transpose
    conv_x_kernel<<<(MPAD * DD / 4 + 255) / 256, 256>>>(x);
    conv_w_kernel<<<dim3(DD / 32, DD / 32, 2), dim3(32, 8)>>>(W_l, W_r);

    // 1) fused fp16 mma.sync GEMM: XL (fp16) and XR (fp32) in one pass over A
    mma_gemm_kernel<<<dim3(DD / BN, MPAD / BM), 256, 2 * STAGE>>>();

    // 2) CSR build by dst (counts pre-zeroed invariant)
    count_kernel<<<(ET + 255) / 256, 256>>>(ei);
    scan_kernel<<<1, 1024>>>();
    scatter_kernel<<<(ET + 255) / 256, 256>>>(ei);

    // 3) fused softmax-aggregate + ELU + residual
    aggregate_kernel<<<(NN * 32 + 255) / 256, 256>>>(x, att, bias, out);
}